// round 8
// baseline (speedup 1.0000x reference)
#include <cuda_runtime.h>
#include <cuda_bf16.h>
#include <cstdint>

// Fixed problem shape: N=100000, E=1250000, IN=6, HID=64.
#define NMAX 100352
#define HID 64

// ---------------- scratch (device globals; 16B aligned) ----------------
__device__ __align__(16) float  g_dis [NMAX];        // fp32 dis (exact path)
__device__ __align__(16) __nv_bfloat16 g_disb[NMAX]; // bf16 dis (scatter w-gather, L1-friendly)
__device__ __align__(16) float  g_w   [NMAX];        // w[src] = sum over out-edges of dis[dst]
__device__ __align__(16) float  g_xs  [NMAX * 8];    // dis-scaled raw features, padded 6->8
__device__ __align__(16) float  g_agg [NMAX * 8];    // edge-aggregated xs (padded)
__device__ __align__(16) double g_u   [HID];         // weighted readout accumulator
__device__ int g_degi[NMAX];                         // self-cleaning (prep zeroes after use)
__device__ int g_is64;

// ---------------- tiny init: detect dtype + zero u ----------------
// int64 little-endian edge data viewed as int32 has every odd word == 0.
__global__ void init_kernel(const int* __restrict__ ei32) {
    int t = threadIdx.x;          // 64 threads
    if (t < HID) g_u[t] = 0.0;
    if (t == 0) {
        int is64 = 1;
        for (int k = 1; k < 128; k += 2)
            if (ei32[k] != 0) { is64 = 0; break; }
        g_is64 = is64;
    }
}

// ---------------- degree count (2 edges per thread) ----------------
__global__ void degcnt_kernel(const int* __restrict__ ei32, int E) {
    int t = blockIdx.x * blockDim.x + threadIdx.x;
    int e0 = t * 2;
    if (e0 >= E) return;
    int d0, d1 = -1;
    if (g_is64) {
        if (e0 + 1 < E) {
            int4 dv = __ldg((const int4*)(ei32 + 2ll * E + 4ll * t));
            d0 = dv.x; d1 = dv.z;
        } else {
            d0 = __ldg(&ei32[2ll * (E + e0)]);
        }
    } else {
        if (e0 + 1 < E) {
            int2 dv = __ldg((const int2*)(ei32 + (long long)E + 2ll * t));
            d0 = dv.x; d1 = dv.y;
        } else {
            d0 = __ldg(&ei32[E + e0]);
        }
    }
    atomicAdd(&g_degi[d0], 1);
    if (d1 >= 0) atomicAdd(&g_degi[d1], 1);
}

// ---------------- prep: dis, xs = x*dis, zero agg/w, self-clean degi ----------------
__global__ void prep_kernel(const float* __restrict__ x, int n) {
    int i = blockIdx.x * blockDim.x + threadIdx.x;
    if (i >= n) return;
    float d = rsqrtf((float)g_degi[i] + 1.0f);
    g_degi[i] = 0;                 // ready for next replay
    g_dis[i]  = d;
    g_disb[i] = __float2bfloat16(d);
    g_w[i]    = 0.0f;
    const float* xi = x + (size_t)i * 6;
    float4 a; float2 b;
    a.x = xi[0] * d;  a.y = xi[1] * d;  a.z = xi[2] * d;  a.w = xi[3] * d;
    b.x = xi[4] * d;  b.y = xi[5] * d;
    ((float4*)(g_xs + (size_t)i * 8))[0] = a;
    ((float2*)(g_xs + (size_t)i * 8))[2] = b;
    ((float4*)(g_agg + (size_t)i * 8))[0] = make_float4(0.f, 0.f, 0.f, 0.f);
    ((float2*)(g_agg + (size_t)i * 8))[2] = make_float2(0.f, 0.f);
}

// ---------------- edge scatter (2 edges per thread) ----------------
// agg[dst] += xs[src] (6 floats: red.v4 + red.v2), w[src] += dis_bf16[dst]
__device__ __forceinline__ void scatter_one(int src, int dst) {
    const float* sp = g_xs + (size_t)src * 8;
    float4 v0 = __ldg((const float4*)sp);
    float2 v1 = __ldg((const float2*)(sp + 4));
    float* p = g_agg + (size_t)dst * 8;
    asm volatile("red.global.add.v4.f32 [%0], {%1,%2,%3,%4};"
                 :: "l"(p), "f"(v0.x), "f"(v0.y), "f"(v0.z), "f"(v0.w) : "memory");
    asm volatile("red.global.add.v2.f32 [%0], {%1,%2};"
                 :: "l"(p + 4), "f"(v1.x), "f"(v1.y) : "memory");
    float dd = __bfloat162float(__ldg(&g_disb[dst]));
    atomicAdd(&g_w[src], dd);
}

__global__ void scatter_kernel(const int* __restrict__ ei32, int E) {
    int t = blockIdx.x * blockDim.x + threadIdx.x;
    int e0 = t * 2;
    if (e0 >= E) return;
    int s0, d0, s1 = -1, d1 = -1;
    if (g_is64) {
        if (e0 + 1 < E) {
            int4 sv = __ldg((const int4*)(ei32 + 4ll * t));
            int4 dv = __ldg((const int4*)(ei32 + 2ll * E + 4ll * t));
            s0 = sv.x; s1 = sv.z; d0 = dv.x; d1 = dv.z;
        } else {
            s0 = __ldg(&ei32[2ll * e0]);
            d0 = __ldg(&ei32[2ll * (E + e0)]);
        }
    } else {
        if (e0 + 1 < E) {
            int2 sv = __ldg((const int2*)(ei32 + 2ll * t));
            int2 dv = __ldg((const int2*)(ei32 + (long long)E + 2ll * t));
            s0 = sv.x; s1 = sv.y; d0 = dv.x; d1 = dv.y;
        } else {
            s0 = __ldg(&ei32[e0]);
            d0 = __ldg(&ei32[E + e0]);
        }
    }
    scatter_one(s0, d0);
    if (s1 >= 0) scatter_one(s1, d1);
}

// ---------------- u[j] = sum_i c[i] * relu( (dis[i]*(agg[i]+xs[i])) . W1[:,j] + b1[j] ) ----------
// c[i] = dis[i]*(w[i]+dis[i]).  256 threads = 4 row-lanes x 64 columns.
__global__ void u_kernel(const float* __restrict__ W1, const float* __restrict__ b1, int n) {
    __shared__ float sW[6 * HID];
    __shared__ float sred[256];
    int tid = threadIdx.x;
    for (int i = tid; i < 6 * HID; i += 256) sW[i] = W1[i];
    __syncthreads();
    int j  = tid & 63;
    int rw = tid >> 6;     // 0..3
    float bj = __ldg(&b1[j]);
    float w0 = sW[0 * HID + j], w1 = sW[1 * HID + j], w2 = sW[2 * HID + j];
    float w3 = sW[3 * HID + j], w4 = sW[4 * HID + j], w5 = sW[5 * HID + j];
    float uacc = 0.0f;
    for (int i = blockIdx.x * 4 + rw; i < n; i += gridDim.x * 4) {
        float d = __ldg(&g_dis[i]);
        const float* ar = g_agg + (size_t)i * 8;
        const float* xr = g_xs  + (size_t)i * 8;
        float4 a0 = __ldg((const float4*)ar);
        float2 a1 = __ldg((const float2*)(ar + 4));
        float4 x0 = __ldg((const float4*)xr);
        float2 x1 = __ldg((const float2*)(xr + 4));
        float v0 = (a0.x + x0.x) * d, v1 = (a0.y + x0.y) * d, v2 = (a0.z + x0.z) * d;
        float v3 = (a0.w + x0.w) * d, v4 = (a1.x + x1.x) * d, v5 = (a1.y + x1.y) * d;
        float h = bj;
        h = fmaf(v0, w0, h); h = fmaf(v1, w1, h); h = fmaf(v2, w2, h);
        h = fmaf(v3, w3, h); h = fmaf(v4, w4, h); h = fmaf(v5, w5, h);
        h = fmaxf(h, 0.0f);
        float c = d * (__ldg(&g_w[i]) + d);
        uacc = fmaf(c, h, uacc);
    }
    sred[tid] = uacc;
    __syncthreads();
    if (tid < HID) {
        double s = (double)sred[tid] + (double)sred[tid + 64]
                 + (double)sred[tid + 128] + (double)sred[tid + 192];
        atomicAdd(&g_u[tid], s);
    }
}

// ---------------- final: sigmoid( ((u @ W2)/n + b2) . Wfc + bfc ) ----------------
__global__ void final_kernel(const float* __restrict__ W2, const float* __restrict__ b2,
                             const float* __restrict__ Wfc, const float* __restrict__ bfc,
                             float* __restrict__ out, int n) {
    __shared__ double s[HID];
    int j = threadIdx.x;   // 64 threads
    double acc = 0.0;
#pragma unroll 8
    for (int k = 0; k < HID; ++k)
        acc += g_u[k] * (double)W2[k * HID + j];
    double t = acc / (double)n + (double)b2[j];
    s[j] = t * (double)Wfc[j];
    __syncthreads();
    if (j < 32) {
        double v = s[j] + s[j + 32];
#pragma unroll
        for (int o = 16; o; o >>= 1) v += __shfl_down_sync(0xffffffff, v, o);
        if (j == 0) {
            double z = v + (double)bfc[0];
            out[0] = (float)(1.0 / (1.0 + exp(-z)));
        }
    }
}

// ================================================================ launch
extern "C" void kernel_launch(void* const* d_in, const int* in_sizes, int n_in,
                              void* d_out, int out_size) {
    const float* x   = (const float*)d_in[0];
    const int*   ei  = (const int*)d_in[1];   // int32 OR int64 (auto-detected on device)
    const float* W1  = (const float*)d_in[2];
    const float* b1  = (const float*)d_in[3];
    const float* W2  = (const float*)d_in[4];
    const float* b2  = (const float*)d_in[5];
    const float* Wfc = (const float*)d_in[6];
    const float* bfc = (const float*)d_in[7];
    float* out = (float*)d_out;

    int n = in_sizes[0] / 6;      // 100000
    int E = in_sizes[1] / 2;      // 1250000
    int npair = (E + 1) / 2;      // edge pairs

    init_kernel<<<1, 64>>>(ei);
    degcnt_kernel<<<(npair + 255) / 256, 256>>>(ei, E);
    prep_kernel<<<(n + 255) / 256, 256>>>(x, n);
    scatter_kernel<<<(npair + 255) / 256, 256>>>(ei, E);
    u_kernel<<<512, 256>>>(W1, b1, n);
    final_kernel<<<1, HID>>>(W2, b2, Wfc, bfc, out, n);
}

// round 9
// speedup vs baseline: 1.0339x; 1.0339x over previous
#include <cuda_runtime.h>
#include <cuda_bf16.h>
#include <cstdint>

// Fixed problem shape: N=100000, E=1250000, IN=6, HID=64.
#define NMAX 100352
#define HID 64

// ---------------- scratch (device globals; 16B aligned) ----------------
__device__ __align__(16) float  g_dis [NMAX];         // fp32 dis (exact path)
__device__ __align__(16) __nv_bfloat16 g_disb[NMAX];  // bf16 dis (scatter gather)
__device__ __align__(16) float  g_w   [NMAX];         // w[src] = sum of dis[dst] over out-edges
__device__ __align__(16) float  g_xs  [NMAX * 8];     // fp32 dis-scaled features (u-kernel self term)
__device__ __align__(16) __nv_bfloat16 g_xsb [NMAX * 8]; // bf16 packed rows (scatter gather), 16B/row
__device__ __align__(16) __nv_bfloat16 g_aggb[NMAX * 8]; // bf16 aggregation rows, 16B/row
__device__ __align__(16) double g_u   [HID];
__device__ int g_degi[NMAX];                          // self-cleaning (prep zeroes after use)
__device__ int g_is64;
__device__ int g_cnt;                                 // u_kernel completion counter (self-resets)

// ---------------- tiny init: detect dtype + zero u ----------------
__global__ void init_kernel(const int* __restrict__ ei32) {
    int t = threadIdx.x;          // 64 threads
    if (t < HID) g_u[t] = 0.0;
    if (t == 0) {
        int is64 = 1;
        for (int k = 1; k < 128; k += 2)
            if (ei32[k] != 0) { is64 = 0; break; }
        g_is64 = is64;
    }
}

// ---------------- degree count (4 edges per thread, vector index loads) ----------------
__global__ void degcnt_kernel(const int* __restrict__ ei32, int E) {
    int t = blockIdx.x * blockDim.x + threadIdx.x;
    int e0 = t * 4;
    if (e0 >= E) return;
    bool full = (e0 + 4 <= E) && ((E & 3) == 0);
    int d[4];
    if (full) {
        if (g_is64) {
            int4 a = __ldg((const int4*)(ei32 + 2ll * E + 8ll * t));
            int4 b = __ldg((const int4*)(ei32 + 2ll * E + 8ll * t + 4));
            d[0] = a.x; d[1] = a.z; d[2] = b.x; d[3] = b.z;
        } else {
            int4 a = __ldg((const int4*)(ei32 + (long long)E + 4ll * t));
            d[0] = a.x; d[1] = a.y; d[2] = a.z; d[3] = a.w;
        }
#pragma unroll
        for (int q = 0; q < 4; ++q) atomicAdd(&g_degi[d[q]], 1);
    } else {
        for (int e = e0; e < E && e < e0 + 4; ++e) {
            int dd = g_is64 ? __ldg(&ei32[2ll * (E + e)]) : __ldg(&ei32[E + e]);
            atomicAdd(&g_degi[dd], 1);
        }
    }
}

// ---------------- prep: dis, xs(fp32)+xsb(bf16), zero aggb/w, self-clean degi ----------------
__global__ void prep_kernel(const float* __restrict__ x, int n) {
    int i = blockIdx.x * blockDim.x + threadIdx.x;
    if (i >= n) return;
    float d = rsqrtf((float)g_degi[i] + 1.0f);
    g_degi[i] = 0;                 // ready for next replay
    g_dis[i]  = d;
    g_disb[i] = __float2bfloat16(d);
    g_w[i]    = 0.0f;
    const float* xi = x + (size_t)i * 6;
    float v[6];
#pragma unroll
    for (int k = 0; k < 6; ++k) v[k] = xi[k] * d;
    // fp32 row (32B)
    ((float4*)(g_xs + (size_t)i * 8))[0] = make_float4(v[0], v[1], v[2], v[3]);
    ((float2*)(g_xs + (size_t)i * 8))[2] = make_float2(v[4], v[5]);
    // bf16 packed row (16B): 6 values + 2 zero pads
    uint4 pk;
    __nv_bfloat162 p0 = __floats2bfloat162_rn(v[0], v[1]);
    __nv_bfloat162 p1 = __floats2bfloat162_rn(v[2], v[3]);
    __nv_bfloat162 p2 = __floats2bfloat162_rn(v[4], v[5]);
    __nv_bfloat162 p3 = __floats2bfloat162_rn(0.f, 0.f);
    pk.x = *reinterpret_cast<uint32_t*>(&p0);
    pk.y = *reinterpret_cast<uint32_t*>(&p1);
    pk.z = *reinterpret_cast<uint32_t*>(&p2);
    pk.w = *reinterpret_cast<uint32_t*>(&p3);
    ((uint4*)g_xsb)[i] = pk;
    ((uint4*)g_aggb)[i] = make_uint4(0u, 0u, 0u, 0u);
}

// ---------------- edge scatter (4 edges per thread) ----------------
// aggb[dst] += xsb[src] (ONE red.v4.bf16x2), w[src] += disb[dst]
__device__ __forceinline__ void scatter_one(int src, int dst) {
    uint4 v = __ldg(((const uint4*)g_xsb) + src);
    __nv_bfloat16* p = g_aggb + (size_t)dst * 8;
    asm volatile("red.global.add.noftz.v4.bf16x2 [%0], {%1,%2,%3,%4};"
                 :: "l"(p), "r"(v.x), "r"(v.y), "r"(v.z), "r"(v.w) : "memory");
    atomicAdd(&g_w[src], __bfloat162float(__ldg(&g_disb[dst])));
}

__global__ void scatter_kernel(const int* __restrict__ ei32, int E) {
    int t = blockIdx.x * blockDim.x + threadIdx.x;
    int e0 = t * 4;
    if (e0 >= E) return;
    bool full = (e0 + 4 <= E) && ((E & 3) == 0);
    if (full) {
        int s[4], d[4];
        if (g_is64) {
            int4 a = __ldg((const int4*)(ei32 + 8ll * t));
            int4 b = __ldg((const int4*)(ei32 + 8ll * t + 4));
            int4 c = __ldg((const int4*)(ei32 + 2ll * E + 8ll * t));
            int4 e = __ldg((const int4*)(ei32 + 2ll * E + 8ll * t + 4));
            s[0] = a.x; s[1] = a.z; s[2] = b.x; s[3] = b.z;
            d[0] = c.x; d[1] = c.z; d[2] = e.x; d[3] = e.z;
        } else {
            int4 a = __ldg((const int4*)(ei32 + 4ll * t));
            int4 c = __ldg((const int4*)(ei32 + (long long)E + 4ll * t));
            s[0] = a.x; s[1] = a.y; s[2] = a.z; s[3] = a.w;
            d[0] = c.x; d[1] = c.y; d[2] = c.z; d[3] = c.w;
        }
#pragma unroll
        for (int q = 0; q < 4; ++q) scatter_one(s[q], d[q]);
    } else {
        for (int e = e0; e < E && e < e0 + 4; ++e) {
            int ss, dd;
            if (g_is64) { ss = __ldg(&ei32[2ll * e]); dd = __ldg(&ei32[2ll * (E + e)]); }
            else        { ss = __ldg(&ei32[e]);       dd = __ldg(&ei32[E + e]); }
            scatter_one(ss, dd);
        }
    }
}

// ---------------- fused u + final ----------------
// u[j] = sum_i c[i]*relu( (dis[i]*(aggb[i]+xs[i])) . W1[:,j] + b1[j] ),  c=dis*(w+dis)
// Last block computes out = sigmoid(((u @ W2)/n + b2) . Wfc + bfc).
__global__ void u_kernel(const float* __restrict__ W1, const float* __restrict__ b1,
                         const float* __restrict__ W2, const float* __restrict__ b2,
                         const float* __restrict__ Wfc, const float* __restrict__ bfc,
                         float* __restrict__ out, int n) {
    __shared__ float sW[6 * HID];
    __shared__ float sred[256];
    __shared__ int isLast;
    int tid = threadIdx.x;
    for (int i = tid; i < 6 * HID; i += 256) sW[i] = W1[i];
    __syncthreads();
    int j  = tid & 63;
    int rw = tid >> 6;     // 0..3
    float bj = __ldg(&b1[j]);
    float w0 = sW[0 * HID + j], w1 = sW[1 * HID + j], w2 = sW[2 * HID + j];
    float w3 = sW[3 * HID + j], w4 = sW[4 * HID + j], w5 = sW[5 * HID + j];
    float uacc = 0.0f;
    for (int i = blockIdx.x * 4 + rw; i < n; i += gridDim.x * 4) {
        float d = __ldg(&g_dis[i]);
        uint4 ap = __ldg(((const uint4*)g_aggb) + i);
        const float* xr = g_xs + (size_t)i * 8;
        float4 x0 = __ldg((const float4*)xr);
        float2 x1 = __ldg((const float2*)(xr + 4));
        float2 a01 = __bfloat1622float2(*reinterpret_cast<const __nv_bfloat162*>(&ap.x));
        float2 a23 = __bfloat1622float2(*reinterpret_cast<const __nv_bfloat162*>(&ap.y));
        float2 a45 = __bfloat1622float2(*reinterpret_cast<const __nv_bfloat162*>(&ap.z));
        float v0 = (a01.x + x0.x) * d, v1 = (a01.y + x0.y) * d, v2 = (a23.x + x0.z) * d;
        float v3 = (a23.y + x0.w) * d, v4 = (a45.x + x1.x) * d, v5 = (a45.y + x1.y) * d;
        float h = bj;
        h = fmaf(v0, w0, h); h = fmaf(v1, w1, h); h = fmaf(v2, w2, h);
        h = fmaf(v3, w3, h); h = fmaf(v4, w4, h); h = fmaf(v5, w5, h);
        h = fmaxf(h, 0.0f);
        float c = d * (__ldg(&g_w[i]) + d);
        uacc = fmaf(c, h, uacc);
    }
    sred[tid] = uacc;
    __syncthreads();
    if (tid < HID) {
        double s = (double)sred[tid] + (double)sred[tid + 64]
                 + (double)sred[tid + 128] + (double)sred[tid + 192];
        atomicAdd(&g_u[tid], s);
    }
    // last-block final
    __threadfence();
    __syncthreads();
    if (tid == 0) {
        int prev = atomicAdd(&g_cnt, 1);
        isLast = (prev == gridDim.x - 1);
        if (isLast) g_cnt = 0;            // self-reset for next replay
    }
    __syncthreads();
    if (!isLast) return;
    __threadfence();                       // acquire all g_u updates
    __shared__ double sf[HID];
    if (tid < HID) {
        double acc = 0.0;
#pragma unroll 8
        for (int k = 0; k < HID; ++k)
            acc += g_u[k] * (double)W2[k * HID + tid];
        double tt = acc / (double)n + (double)b2[tid];
        sf[tid] = tt * (double)Wfc[tid];
    }
    __syncthreads();
    if (tid < 32) {
        double v = sf[tid] + sf[tid + 32];
#pragma unroll
        for (int o = 16; o; o >>= 1) v += __shfl_down_sync(0xffffffff, v, o);
        if (tid == 0) {
            double z = v + (double)bfc[0];
            out[0] = (float)(1.0 / (1.0 + exp(-z)));
        }
    }
}

// ================================================================ launch
extern "C" void kernel_launch(void* const* d_in, const int* in_sizes, int n_in,
                              void* d_out, int out_size) {
    const float* x   = (const float*)d_in[0];
    const int*   ei  = (const int*)d_in[1];   // int32 OR int64 (auto-detected on device)
    const float* W1  = (const float*)d_in[2];
    const float* b1  = (const float*)d_in[3];
    const float* W2  = (const float*)d_in[4];
    const float* b2  = (const float*)d_in[5];
    const float* Wfc = (const float*)d_in[6];
    const float* bfc = (const float*)d_in[7];
    float* out = (float*)d_out;

    int n = in_sizes[0] / 6;      // 100000
    int E = in_sizes[1] / 2;      // 1250000
    int nq = (E + 3) / 4;         // edge quads

    init_kernel<<<1, 64>>>(ei);
    degcnt_kernel<<<(nq + 255) / 256, 256>>>(ei, E);
    prep_kernel<<<(n + 255) / 256, 256>>>(x, n);
    scatter_kernel<<<(nq + 255) / 256, 256>>>(ei, E);
    u_kernel<<<512, 256>>>(W1, b1, W2, b2, Wfc, bfc, out, n);
}

// round 10
// speedup vs baseline: 1.0857x; 1.0501x over previous
#include <cuda_runtime.h>
#include <cuda_bf16.h>
#include <cstdint>

// Fixed problem shape: N=100000, E=1250000, IN=6, HID=64.
#define NMAX 100352
#define HID 64

// ---------------- scratch (device globals; 16B aligned) ----------------
__device__ __align__(16) float  g_dis [NMAX];            // fp32 dis
__device__ __align__(16) __nv_bfloat16 g_disb[NMAX];     // bf16 dis (scatter gather)
__device__ __align__(16) float  g_w   [NMAX];            // w[src] = sum of dis[dst]
__device__ __align__(16) __nv_bfloat16 g_xsb [NMAX * 8]; // bf16 packed feature rows, 16B/row
__device__ __align__(16) __nv_bfloat16 g_aggb[NMAX * 8]; // bf16 agg rows, init = xsb (self-loop)
__device__ __align__(16) double g_u   [HID];
__device__ int g_degi[NMAX];                             // self-cleaning
__device__ int g_is64;
__device__ int g_cnt;                                    // u completion counter (self-resets)

// ---------------- tiny init: detect dtype + zero u ----------------
__global__ void init_kernel(const int* __restrict__ ei32) {
    int t = threadIdx.x;          // 64 threads
    if (t < HID) g_u[t] = 0.0;
    if (t == 0) {
        int is64 = 1;
        for (int k = 1; k < 128; k += 2)
            if (ei32[k] != 0) { is64 = 0; break; }
        g_is64 = is64;
    }
}

// ---------------- degree count (8 edges per thread) ----------------
__global__ void degcnt_kernel(const int* __restrict__ ei32, int E) {
    long long t = blockIdx.x * blockDim.x + threadIdx.x;
    long long e0 = t * 8;
    if (e0 >= E) return;
    if (e0 + 8 <= E) {
        int d[8];
        if (g_is64) {
            const int4* p = (const int4*)(ei32 + 2ll * E) + t * 4;
            int4 a = __ldg(p), b = __ldg(p + 1), c = __ldg(p + 2), e = __ldg(p + 3);
            d[0] = a.x; d[1] = a.z; d[2] = b.x; d[3] = b.z;
            d[4] = c.x; d[5] = c.z; d[6] = e.x; d[7] = e.z;
        } else {
            const int4* p = (const int4*)(ei32 + (long long)E) + t * 2;
            int4 a = __ldg(p), b = __ldg(p + 1);
            d[0] = a.x; d[1] = a.y; d[2] = a.z; d[3] = a.w;
            d[4] = b.x; d[5] = b.y; d[6] = b.z; d[7] = b.w;
        }
#pragma unroll
        for (int q = 0; q < 8; ++q) atomicAdd(&g_degi[d[q]], 1);
    } else {
        for (long long e = e0; e < E; ++e) {
            int dd = g_is64 ? __ldg(&ei32[2ll * (E + e)]) : __ldg(&ei32[E + e]);
            atomicAdd(&g_degi[dd], 1);
        }
    }
}

// ---------------- prep: dis, xsb, aggb=xsb (self-loop), w=0, self-clean degi ----------------
__global__ void prep_kernel(const float* __restrict__ x, int n) {
    int i = blockIdx.x * blockDim.x + threadIdx.x;
    if (i >= n) return;
    float d = rsqrtf((float)g_degi[i] + 1.0f);
    g_degi[i] = 0;
    g_dis[i]  = d;
    g_disb[i] = __float2bfloat16(d);
    g_w[i]    = 0.0f;
    const float* xi = x + (size_t)i * 6;
    __nv_bfloat162 p0 = __floats2bfloat162_rn(xi[0] * d, xi[1] * d);
    __nv_bfloat162 p1 = __floats2bfloat162_rn(xi[2] * d, xi[3] * d);
    __nv_bfloat162 p2 = __floats2bfloat162_rn(xi[4] * d, xi[5] * d);
    uint4 pk;
    pk.x = *reinterpret_cast<uint32_t*>(&p0);
    pk.y = *reinterpret_cast<uint32_t*>(&p1);
    pk.z = *reinterpret_cast<uint32_t*>(&p2);
    pk.w = 0u;
    ((uint4*)g_xsb)[i]  = pk;
    ((uint4*)g_aggb)[i] = pk;     // self-loop pre-seeded
}

// ---------------- edge scatter (8 edges per thread, gather/red split) ----------------
__global__ void scatter_kernel(const int* __restrict__ ei32, int E) {
    long long t = blockIdx.x * blockDim.x + threadIdx.x;
    long long e0 = t * 8;
    if (e0 >= E) return;
    if (e0 + 8 <= E) {
        int s[8], d[8];
        if (g_is64) {
            const int4* ps = (const int4*)ei32 + t * 4;
            const int4* pd = (const int4*)(ei32 + 2ll * E) + t * 4;
            int4 a = __ldg(ps), b = __ldg(ps + 1), c = __ldg(ps + 2), e = __ldg(ps + 3);
            int4 f = __ldg(pd), g = __ldg(pd + 1), h = __ldg(pd + 2), m = __ldg(pd + 3);
            s[0] = a.x; s[1] = a.z; s[2] = b.x; s[3] = b.z;
            s[4] = c.x; s[5] = c.z; s[6] = e.x; s[7] = e.z;
            d[0] = f.x; d[1] = f.z; d[2] = g.x; d[3] = g.z;
            d[4] = h.x; d[5] = h.z; d[6] = m.x; d[7] = m.z;
        } else {
            const int4* ps = (const int4*)ei32 + t * 2;
            const int4* pd = (const int4*)(ei32 + (long long)E) + t * 2;
            int4 a = __ldg(ps), b = __ldg(ps + 1);
            int4 f = __ldg(pd), g = __ldg(pd + 1);
            s[0] = a.x; s[1] = a.y; s[2] = a.z; s[3] = a.w;
            s[4] = b.x; s[5] = b.y; s[6] = b.z; s[7] = b.w;
            d[0] = f.x; d[1] = f.y; d[2] = f.z; d[3] = f.w;
            d[4] = g.x; d[5] = g.y; d[6] = g.z; d[7] = g.w;
        }
        // issue all gathers first (max MLP)
        uint4 v[8];
        float dd[8];
#pragma unroll
        for (int q = 0; q < 8; ++q) v[q] = __ldg(((const uint4*)g_xsb) + s[q]);
#pragma unroll
        for (int q = 0; q < 8; ++q) dd[q] = __bfloat162float(__ldg(&g_disb[d[q]]));
        // then all reductions (fire-and-forget)
#pragma unroll
        for (int q = 0; q < 8; ++q) {
            __nv_bfloat16* p = g_aggb + (size_t)d[q] * 8;
            asm volatile("red.global.add.noftz.v4.bf16x2 [%0], {%1,%2,%3,%4};"
                         :: "l"(p), "r"(v[q].x), "r"(v[q].y), "r"(v[q].z), "r"(v[q].w) : "memory");
            atomicAdd(&g_w[s[q]], dd[q]);
        }
    } else {
        for (long long e = e0; e < E; ++e) {
            int ss, dd;
            if (g_is64) { ss = __ldg(&ei32[2ll * e]); dd = __ldg(&ei32[2ll * (E + e)]); }
            else        { ss = __ldg(&ei32[e]);       dd = __ldg(&ei32[E + e]); }
            uint4 v = __ldg(((const uint4*)g_xsb) + ss);
            __nv_bfloat16* p = g_aggb + (size_t)dd * 8;
            asm volatile("red.global.add.noftz.v4.bf16x2 [%0], {%1,%2,%3,%4};"
                         :: "l"(p), "r"(v.x), "r"(v.y), "r"(v.z), "r"(v.w) : "memory");
            atomicAdd(&g_w[ss], __bfloat162float(__ldg(&g_disb[dd])));
        }
    }
}

// ---------------- fused u + final ----------------
// u[j] = sum_i c[i]*relu( (dis[i]*aggb[i]) . W1[:,j] + b1[j] ),  c=dis*(w+dis)
// (aggb already includes the self term.)  Last block computes the head.
__global__ void u_kernel(const float* __restrict__ W1, const float* __restrict__ b1,
                         const float* __restrict__ W2, const float* __restrict__ b2,
                         const float* __restrict__ Wfc, const float* __restrict__ bfc,
                         float* __restrict__ out, int n) {
    __shared__ float sW[6 * HID];
    __shared__ float sred[256];
    __shared__ int isLast;
    int tid = threadIdx.x;
    for (int i = tid; i < 6 * HID; i += 256) sW[i] = W1[i];
    __syncthreads();
    int j  = tid & 63;
    int rw = tid >> 6;     // 0..3
    float bj = __ldg(&b1[j]);
    float w0 = sW[0 * HID + j], w1 = sW[1 * HID + j], w2 = sW[2 * HID + j];
    float w3 = sW[3 * HID + j], w4 = sW[4 * HID + j], w5 = sW[5 * HID + j];
    float uacc = 0.0f;
    for (int i = blockIdx.x * 4 + rw; i < n; i += gridDim.x * 4) {
        float d = __ldg(&g_dis[i]);
        uint4 ap = __ldg(((const uint4*)g_aggb) + i);
        float2 a01 = __bfloat1622float2(*reinterpret_cast<const __nv_bfloat162*>(&ap.x));
        float2 a23 = __bfloat1622float2(*reinterpret_cast<const __nv_bfloat162*>(&ap.y));
        float2 a45 = __bfloat1622float2(*reinterpret_cast<const __nv_bfloat162*>(&ap.z));
        float h = bj;
        h = fmaf(a01.x * d, w0, h); h = fmaf(a01.y * d, w1, h);
        h = fmaf(a23.x * d, w2, h); h = fmaf(a23.y * d, w3, h);
        h = fmaf(a45.x * d, w4, h); h = fmaf(a45.y * d, w5, h);
        h = fmaxf(h, 0.0f);
        float c = d * (__ldg(&g_w[i]) + d);
        uacc = fmaf(c, h, uacc);
    }
    sred[tid] = uacc;
    __syncthreads();
    if (tid < HID) {
        double s = (double)sred[tid] + (double)sred[tid + 64]
                 + (double)sred[tid + 128] + (double)sred[tid + 192];
        atomicAdd(&g_u[tid], s);
    }
    __threadfence();
    __syncthreads();
    if (tid == 0) {
        int prev = atomicAdd(&g_cnt, 1);
        isLast = (prev == gridDim.x - 1);
        if (isLast) g_cnt = 0;
    }
    __syncthreads();
    if (!isLast) return;
    __threadfence();
    __shared__ double sf[HID];
    if (tid < HID) {
        double acc = 0.0;
#pragma unroll 8
        for (int k = 0; k < HID; ++k)
            acc += g_u[k] * (double)W2[k * HID + tid];
        double tt = acc / (double)n + (double)b2[tid];
        sf[tid] = tt * (double)Wfc[tid];
    }
    __syncthreads();
    if (tid < 32) {
        double v = sf[tid] + sf[tid + 32];
#pragma unroll
        for (int o = 16; o; o >>= 1) v += __shfl_down_sync(0xffffffff, v, o);
        if (tid == 0) {
            double z = v + (double)bfc[0];
            out[0] = (float)(1.0 / (1.0 + exp(-z)));
        }
    }
}

// ================================================================ launch
extern "C" void kernel_launch(void* const* d_in, const int* in_sizes, int n_in,
                              void* d_out, int out_size) {
    const float* x   = (const float*)d_in[0];
    const int*   ei  = (const int*)d_in[1];   // int32 OR int64 (auto-detected on device)
    const float* W1  = (const float*)d_in[2];
    const float* b1  = (const float*)d_in[3];
    const float* W2  = (const float*)d_in[4];
    const float* b2  = (const float*)d_in[5];
    const float* Wfc = (const float*)d_in[6];
    const float* bfc = (const float*)d_in[7];
    float* out = (float*)d_out;

    int n = in_sizes[0] / 6;      // 100000
    int E = in_sizes[1] / 2;      // 1250000
    int n8 = (E + 7) / 8;         // edge octets

    init_kernel<<<1, 64>>>(ei);
    degcnt_kernel<<<(n8 + 255) / 256, 256>>>(ei, E);
    prep_kernel<<<(n + 255) / 256, 256>>>(x, n);
    scatter_kernel<<<(n8 + 255) / 256, 256>>>(ei, E);
    u_kernel<<<512, 256>>>(W1, b1, W2, b2, Wfc, bfc, out, n);
}